// round 15
// baseline (speedup 1.0000x reference)
#include <cuda_runtime.h>
#include <cuda_fp16.h>
#include <cstdint>
#include <stdint.h>
#include <math.h>

#define Bn   2
#define Sn   2048
#define HIDn 1536
#define Hn   12
#define HDn  128
#define TOKn (Bn*Sn)   // 4096

// ---------------- scratch (device globals; no allocations allowed) ----------
__device__ __half g_hs16[(size_t)TOKn*1536];     // hidden single fp16
__device__ __half g_Wqkv[(size_t)384*1536];      // [n][k] single fp16
__device__ __half g_Wkv [(size_t)2304*192];
__device__ __half g_Wq  [(size_t)1536*192];
__device__ __half g_Wrk [(size_t)768*1536];
__device__ __half g_Wob [(size_t)1536*1536];
__device__ __half g_dA1 [(size_t)TOKn*384];      // [tok][kvd192|qd192] single fp16
__device__ __half g_kcvf[(size_t)TOKn*2304];     // fp16
__device__ __half g_qcqr[(size_t)TOKn*1536];     // fp16
__device__ __half g_krb [(size_t)TOKn*768];      // fp16
__device__ __half g_qb[(size_t)Bn*Hn*Sn*128];    // Q single fp16 (scaled)
__device__ __half g_kb[(size_t)Bn*Hn*Sn*128];    // K single
__device__ __half g_vb[(size_t)Bn*Hn*Sn*128];    // V single
__device__ __half g_at1[(size_t)TOKn*1536];      // attn out single fp16

// ---------------- helpers ----------------------------------------------------
__device__ __forceinline__ unsigned pack2h(float a, float b) {
  __half2 t = __floats2half2_rn(a, b);
  return *(unsigned*)&t;
}

#define MMAF16(d0,d1,d2,d3,a0,a1,a2,a3,b0,b1)                              \
  asm volatile("mma.sync.aligned.m16n8k16.row.col.f32.f16.f16.f32 "         \
    "{%0,%1,%2,%3},{%4,%5,%6,%7},{%8,%9},{%0,%1,%2,%3};"                    \
    : "+f"(d0),"+f"(d1),"+f"(d2),"+f"(d3)                                    \
    : "r"(a0),"r"(a1),"r"(a2),"r"(a3),"r"(b0),"r"(b1))
#define LDSM_X4(r0,r1,r2,r3,addr)                                           \
  asm volatile("ldmatrix.sync.aligned.m8n8.x4.shared.b16 "                  \
    "{%0,%1,%2,%3},[%4];"                                                   \
    : "=r"(r0),"=r"(r1),"=r"(r2),"=r"(r3) : "r"(addr))
#define LDSM_X4T(r0,r1,r2,r3,addr)                                          \
  asm volatile("ldmatrix.sync.aligned.m8n8.x4.trans.shared.b16 "            \
    "{%0,%1,%2,%3},[%4];"                                                   \
    : "=r"(r0),"=r"(r1),"=r"(r2),"=r"(r3) : "r"(addr))
#define CPASYNC16(dst, src)                                                 \
  asm volatile("cp.async.cg.shared.global [%0],[%1],16;" :: "r"(dst), "l"(src))

// ---------------- conversion kernels ----------------------------------------
__global__ __launch_bounds__(256)
void convA_kernel(const float4* __restrict__ X, __half* __restrict__ Y) {
  size_t i = (size_t)blockIdx.x*256 + threadIdx.x;
  float4 v = X[i];
  __half2 h0 = __floats2half2_rn(v.x, v.y);
  __half2 h1 = __floats2half2_rn(v.z, v.w);
  *(__half2*)(Y + i*4)     = h0;
  *(__half2*)(Y + i*4 + 2) = h1;
}

struct ConvJobs {
  const float* W[8];
  __half* Bt[8];
  int K[8], N[8];
  int bstart[9];
};
__global__ __launch_bounds__(256)
void convW_kernel(ConvJobs J) {
  __shared__ float t[32][33];
  int bx = blockIdx.x;
  int j = 0;
  while (bx >= J.bstart[j+1]) j++;
  int lb = bx - J.bstart[j];
  int nbn = J.N[j] >> 5;
  int n0 = (lb % nbn) << 5, k0 = (lb / nbn) << 5;
  const float* W = J.W[j];
  __half* Bt = J.Bt[j];
  int K = J.K[j], N = J.N[j];
  #pragma unroll
  for (int i = threadIdx.y; i < 32; i += 8)
    t[i][threadIdx.x] = W[(size_t)(k0+i)*N + n0 + threadIdx.x];
  __syncthreads();
  #pragma unroll
  for (int i = threadIdx.y; i < 32; i += 8) {
    int n = n0 + i, k = k0 + threadIdx.x;
    Bt[(size_t)n*K + k] = __float2half(t[threadIdx.x][i]);
  }
}

// ---------------- fp16 tensor-core GEMM (batched, 3-stage, BK=64) -----------
struct GJob {
  const __half *Am, *Bm;
  float* C; __half* Cb;
  int lda, N, K, outmode, nbx;
};
struct GJobs { GJob j[3]; int bstart[4]; };

template<int BN, int NJ>
__global__ __launch_bounds__(256)
void hgemm_kernel(GJobs JB) {
  constexpr int BOFF  = 128*72;
  constexpr int STAGE = (128 + BN)*72;
  constexpr int WN = BN/32, WM = 8/WN, MT = 128/(WM*16);

  extern __shared__ __half hsm[];
  int tid = threadIdx.x;
  int bid = blockIdx.x;
  int ji = 0;
  #pragma unroll
  for (int t = 1; t < NJ; t++) if (bid >= JB.bstart[t]) ji = t;
  GJob jb = JB.j[ji];
  int lb = bid - JB.bstart[ji];
  int bx = lb % jb.nbx, by = lb / jb.nbx;
  const __half* Am = jb.Am;
  const __half* Bm = jb.Bm;
  int lda = jb.lda, N = jb.N, K = jb.K;
  int KIT = K >> 6;

  auto load_st = [&](int it, int slot) {
    int kk = it << 6;
    __half* dst = hsm + slot*STAGE;
    #pragma unroll
    for (int p = 0; p < 4; p++) {
      int u = tid + (p << 8);
      int row = u >> 3, c = u & 7;
      size_t ga = (size_t)(by*128 + row)*lda + kk + c*8;
      unsigned dh = (unsigned)__cvta_generic_to_shared(dst + row*72 + c*8);
      CPASYNC16(dh, Am + ga);
    }
    #pragma unroll
    for (int p = 0; p < BN/32; p++) {
      int u = tid + (p << 8);
      int row = u >> 3, c = u & 7;
      const __half* sB = Bm + (size_t)(bx*BN + row)*K + kk + c*8;
      unsigned db = (unsigned)__cvta_generic_to_shared(dst + BOFF + row*72 + c*8);
      CPASYNC16(db, sB);
    }
    asm volatile("cp.async.commit_group;");
  };

  int wid = tid >> 5, lane = tid & 31;
  int wm = wid / WN, wn = wid % WN;
  int g = lane >> 2, tig = lane & 3;
  int lr = lane & 15, lc = (lane >> 4) << 3;

  float acc[MT][4][4];
  #pragma unroll
  for (int mt=0; mt<MT; mt++)
    #pragma unroll
    for (int nt=0; nt<4; nt++)
      #pragma unroll
      for (int r=0; r<4; r++) acc[mt][nt][r] = 0.f;

  load_st(0, 0);
  load_st(1, 1);

  for (int it = 0; it < KIT; ++it) {
    if (it + 1 < KIT) asm volatile("cp.async.wait_group 1;");
    else              asm volatile("cp.async.wait_group 0;");
    __syncthreads();
    if (it + 2 < KIT) load_st(it + 2, (it + 2) % 3);
    const __half* St = hsm + (it % 3)*STAGE;

    #pragma unroll
    for (int ks = 0; ks < 4; ks++) {
      unsigned b[4][2];
      #pragma unroll
      for (int bt = 0; bt < 2; bt++) {
        unsigned q0,q1,q2,q3;
        unsigned bd = (unsigned)__cvta_generic_to_shared(
            St + BOFF + (wn*32 + bt*16 + lr)*72 + ks*16 + lc);
        LDSM_X4(q0,q1,q2,q3, bd);
        b[2*bt  ][0] = q0; b[2*bt  ][1] = q2;
        b[2*bt+1][0] = q1; b[2*bt+1][1] = q3;
      }
      unsigned a[MT][4];
      #pragma unroll
      for (int mt = 0; mt < MT; mt++) {
        unsigned ad = (unsigned)__cvta_generic_to_shared(
            St + (wm*(MT*16) + mt*16 + lr)*72 + ks*16 + lc);
        LDSM_X4(a[mt][0], a[mt][1], a[mt][2], a[mt][3], ad);
      }
      #pragma unroll
      for (int mt = 0; mt < MT; mt++)
        #pragma unroll
        for (int nt = 0; nt < 4; nt++)
          MMAF16(acc[mt][nt][0],acc[mt][nt][1],acc[mt][nt][2],acc[mt][nt][3],
                 a[mt][0],a[mt][1],a[mt][2],a[mt][3],
                 b[nt][0],b[nt][1]);
    }
  }

  #pragma unroll
  for (int mt = 0; mt < MT; mt++) {
    #pragma unroll
    for (int nt = 0; nt < 4; nt++) {
      int row = by*128 + wm*(MT*16) + mt*16 + g;
      int col = bx*BN + wn*32 + nt*8 + 2*tig;
      if (jb.outmode == 0) {
        float2 v0 = make_float2(acc[mt][nt][0], acc[mt][nt][1]);
        float2 v1 = make_float2(acc[mt][nt][2], acc[mt][nt][3]);
        *(float2*)&jb.C[(size_t)row    *N + col] = v0;
        *(float2*)&jb.C[(size_t)(row+8)*N + col] = v1;
      } else {
        *(__half2*)&jb.Cb[(size_t)row    *N + col] =
            __floats2half2_rn(acc[mt][nt][0], acc[mt][nt][1]);
        *(__half2*)&jb.Cb[(size_t)(row+8)*N + col] =
            __floats2half2_rn(acc[mt][nt][2], acc[mt][nt][3]);
      }
    }
  }
}

// ---------------- assemble: RoPE + layout + scale (coalesced) ---------------
__global__ __launch_bounds__(256)
void assemble_kernel(const __half* __restrict__ qcqr, const __half* __restrict__ kcvf,
                     const __half* __restrict__ krb, const float* __restrict__ rot,
                     __half* __restrict__ Qh, __half* __restrict__ Kh,
                     __half* __restrict__ Vh) {
  int s = blockIdx.x, b = blockIdx.y;
  int tid = threadIdx.x;
  int token = b*Sn + s;
  const float* rrow = rot + (size_t)s*64;
  const float SCALE = 0.08838834764831845f * 1.4426950408889634f;

  #pragma unroll
  for (int it = 0; it < 6; it++) {
    int lin = it*256 + tid;
    int h = lin >> 7, d = lin & 127;
    size_t bhs = (size_t)(b*Hn + h)*Sn + s;

    Vh[bhs*128 + d] = kcvf[(size_t)token*2304 + 768 + h*HDn + d];

    float qv, kv;
    if (d < 64) {
      qv = __half2float(qcqr[(size_t)token*1536 + h*64 + d]);
      kv = __half2float(kcvf[(size_t)token*2304 + h*64 + d]);
    } else {
      int i = d - 64;
      const __half* qrow = qcqr + (size_t)token*1536 + 768 + h*64;
      const __half* krow = krb + (size_t)token*768 + h*64;
      if (i < 32) {
        float sn = rrow[i], cs = rrow[32+i];
        qv = __half2float(qrow[i])*cs - __half2float(qrow[i+32])*sn;
        kv = __half2float(krow[i])*cs - __half2float(krow[i+32])*sn;
      } else {
        int ii = i - 32;
        float sn = rrow[ii], cs = rrow[32+ii];
        qv = __half2float(qrow[ii])*sn + __half2float(qrow[ii+32])*cs;
        kv = __half2float(krow[ii])*sn + __half2float(krow[ii+32])*cs;
      }
    }
    Qh[bhs*128 + d] = __float2half(qv * SCALE);
    Kh[bhs*128 + d] = __float2half(kv);
  }
}

// ---------------- causal flash attention: paired q-tiles ---------------------
// grid (24 bh, 8 pairs). Block does q-tiles (15-pair) then (pair):
// total iterations = 34 for EVERY block -> perfectly balanced single wave.
#define FLASH_SMEM 104448

__global__ __launch_bounds__(256, 2)
void flash_kernel(const __half* __restrict__ Qg,
                  const __half* __restrict__ Kg,
                  const __half* __restrict__ Vg,
                  __half* __restrict__ At) {
  extern __shared__ __half fsm[];
  __half* Qs = fsm;              // [128][136]
  __half* Ks = fsm + 17408;      // [2 buf][64][136]
  __half* Vs = fsm + 34816;      // [2 buf][64][136]

  int bh = (int)blockIdx.x;          // 0..23
  int pr = (int)blockIdx.y;          // 0..7
  int h = bh % Hn, b = bh / Hn;
  const __half* Kb = Kg + (size_t)bh*Sn*128;
  const __half* Vb = Vg + (size_t)bh*Sn*128;

  int tid = threadIdx.x;
  int wid = tid>>5, lane = tid&31, g = lane>>2, tig = lane&3;
  int lr = lane & 15, lc = (lane >> 4) << 3;
  int r0 = wid*16;

  auto load_kv = [&](int jt, int buf){
    #pragma unroll
    for (int p=0;p<4;p++){
      int lin = tid + p*256;
      int row = lin>>4, c = lin&15;
      size_t s_off = (size_t)(jt*64 + row)*128 + c*8;
      int doff = buf*8704 + row*136 + c*8;
      unsigned dk = (unsigned)__cvta_generic_to_shared(Ks + doff);
      CPASYNC16(dk, Kb + s_off);
      unsigned dv = (unsigned)__cvta_generic_to_shared(Vs + doff);
      CPASYNC16(dv, Vb + s_off);
    }
    asm volatile("cp.async.commit_group;");
  };

  #pragma unroll 1
  for (int phase = 0; phase < 2; phase++) {
    int qi = phase ? pr : 15 - pr;     // long tile first
    int qbase = qi*128;
    int jmax = 2*qi + 2;
    const __half* Qb = Qg + ((size_t)bh*Sn + qbase)*128;

    if (phase) __syncthreads();        // all warps done reading Qs/Ks/Vs

    // Q load (joins commit group with first K/V tiles)
    #pragma unroll
    for (int p=0;p<8;p++){
      int lin = tid + p*256;
      int row = lin>>4, c = lin&15;
      const __half* src = Qb + (size_t)row*128 + c*8;
      unsigned d = (unsigned)__cvta_generic_to_shared(Qs + row*136 + c*8);
      CPASYNC16(d, src);
    }
    load_kv(0, 0);

    float o[16][4];
    #pragma unroll
    for (int nt=0;nt<16;nt++)
      #pragma unroll
      for (int r=0;r<4;r++) o[nt][r] = 0.f;
    float m0=-1e30f, m1=-1e30f, l0=0.f, l1=0.f;

    for (int jt = 0; jt < jmax; jt++) {
      int buf = jt & 1;
      asm volatile("cp.async.wait_group 0;");
      __syncthreads();
      if (jt + 1 < jmax) load_kv(jt+1, buf^1);

      const __half* Kbuf = Ks + buf*8704;
      float acc[8][4];
      #pragma unroll
      for (int t=0;t<8;t++)
        #pragma unroll
        for (int r=0;r<4;r++) acc[t][r] = 0.f;

      #pragma unroll
      for (int ks=0; ks<8; ks++){
        unsigned ah[4];
        {
          unsigned qd = (unsigned)__cvta_generic_to_shared(
              Qs + (r0 + lr)*136 + ks*16 + lc);
          LDSM_X4(ah[0],ah[1],ah[2],ah[3], qd);
        }
        unsigned bk[8][2];
        #pragma unroll
        for (int t16=0; t16<4; t16++){
          unsigned q0,q1,q2,q3;
          unsigned kd = (unsigned)__cvta_generic_to_shared(
              Kbuf + (t16*16 + lr)*136 + ks*16 + lc);
          LDSM_X4(q0,q1,q2,q3, kd);
          bk[2*t16  ][0] = q0; bk[2*t16  ][1] = q2;
          bk[2*t16+1][0] = q1; bk[2*t16+1][1] = q3;
        }
        #pragma unroll
        for (int t=0;t<8;t++)
          MMAF16(acc[t][0],acc[t][1],acc[t][2],acc[t][3],
                 ah[0],ah[1],ah[2],ah[3], bk[t][0],bk[t][1]);
      }

      if (jt >= jmax-2) {
        int rg0 = qbase + r0 + g, rg1 = rg0 + 8;
        #pragma unroll
        for (int t=0;t<8;t++){
          int c0 = jt*64 + t*8 + 2*tig;
          if (c0   > rg0) acc[t][0] = -1e30f;
          if (c0+1 > rg0) acc[t][1] = -1e30f;
          if (c0   > rg1) acc[t][2] = -1e30f;
          if (c0+1 > rg1) acc[t][3] = -1e30f;
        }
      }

      float mx0=-1e30f, mx1=-1e30f;
      #pragma unroll
      for (int t=0;t<8;t++){
        mx0 = fmaxf(mx0, fmaxf(acc[t][0],acc[t][1]));
        mx1 = fmaxf(mx1, fmaxf(acc[t][2],acc[t][3]));
      }
      mx0 = fmaxf(mx0, __shfl_xor_sync(0xffffffffu, mx0, 1));
      mx0 = fmaxf(mx0, __shfl_xor_sync(0xffffffffu, mx0, 2));
      mx1 = fmaxf(mx1, __shfl_xor_sync(0xffffffffu, mx1, 1));
      mx1 = fmaxf(mx1, __shfl_xor_sync(0xffffffffu, mx1, 2));
      float nm0 = fmaxf(m0, mx0), nm1 = fmaxf(m1, mx1);
      float cf0 = exp2f(m0 - nm0), cf1 = exp2f(m1 - nm1);
      m0 = nm0; m1 = nm1;
      float s0 = 0.f, s1 = 0.f;
      #pragma unroll
      for (int t=0;t<8;t++){
        acc[t][0] = exp2f(acc[t][0]-nm0);
        acc[t][1] = exp2f(acc[t][1]-nm0);
        acc[t][2] = exp2f(acc[t][2]-nm1);
        acc[t][3] = exp2f(acc[t][3]-nm1);
        s0 += acc[t][0]+acc[t][1];
        s1 += acc[t][2]+acc[t][3];
      }
      s0 += __shfl_xor_sync(0xffffffffu, s0, 1);
      s0 += __shfl_xor_sync(0xffffffffu, s0, 2);
      s1 += __shfl_xor_sync(0xffffffffu, s1, 1);
      s1 += __shfl_xor_sync(0xffffffffu, s1, 2);
      l0 = l0*cf0 + s0;
      l1 = l1*cf1 + s1;
      #pragma unroll
      for (int nt=0;nt<16;nt++){
        o[nt][0] *= cf0; o[nt][1] *= cf0;
        o[nt][2] *= cf1; o[nt][3] *= cf1;
      }

      const __half* Vbuf = Vs + buf*8704;
      int vrow = ((lane>>3)&1)*8 + (lane&7);
      int vcol = (lane>>4)*8;
      #pragma unroll
      for (int u=0;u<4;u++){
        unsigned ph[4];
        ph[0] = pack2h(acc[2*u  ][0], acc[2*u  ][1]);
        ph[1] = pack2h(acc[2*u  ][2], acc[2*u  ][3]);
        ph[2] = pack2h(acc[2*u+1][0], acc[2*u+1][1]);
        ph[3] = pack2h(acc[2*u+1][2], acc[2*u+1][3]);
        unsigned base = (unsigned)__cvta_generic_to_shared(
            Vbuf + (u*16 + vrow)*136 + vcol);
        #pragma unroll
        for (int dt=0;dt<8;dt++){
          unsigned v0,v1,v2,v3;
          LDSM_X4T(v0,v1,v2,v3, base + dt*32);
          MMAF16(o[dt*2  ][0],o[dt*2  ][1],o[dt*2  ][2],o[dt*2  ][3],
                 ph[0],ph[1],ph[2],ph[3], v0,v1);
          MMAF16(o[dt*2+1][0],o[dt*2+1][1],o[dt*2+1][2],o[dt*2+1][3],
                 ph[0],ph[1],ph[2],ph[3], v2,v3);
        }
      }
    }

    // epilogue for this phase
    float i0 = 1.f/l0, i1 = 1.f/l1;
    int tok0 = b*Sn + qbase + r0 + g;
    __half* o0 = At + (size_t)tok0*1536 + h*128;
    __half* o1 = At + (size_t)(tok0+8)*1536 + h*128;
    #pragma unroll
    for (int nt=0;nt<16;nt++){
      int col = nt*8 + 2*tig;
      *(__half2*)(o0 + col) = __floats2half2_rn(o[nt][0]*i0, o[nt][1]*i0);
      *(__half2*)(o1 + col) = __floats2half2_rn(o[nt][2]*i1, o[nt][3]*i1);
    }
  }
}

// ---------------- launch -----------------------------------------------------
extern "C" void kernel_launch(void* const* d_in, const int* in_sizes, int n_in,
                              void* d_out, int out_size) {
  (void)in_sizes; (void)n_in; (void)out_size;
  const float* hs   = (const float*)d_in[0];
  const float* rot  = (const float*)d_in[1];
  const float* Wkvd = (const float*)d_in[2];
  const float* Wqd  = (const float*)d_in[3];
  const float* Wku  = (const float*)d_in[4];
  const float* Wqu  = (const float*)d_in[5];
  const float* Wvu  = (const float*)d_in[6];
  const float* Wrk  = (const float*)d_in[7];
  const float* Wrq  = (const float*)d_in[8];
  const float* Wo   = (const float*)d_in[9];
  float* out = (float*)d_out;

  __half *hs16,*wqkv,*wkv,*wq,*wrk,*wob,*dA1,*at1,*qb,*kb,*vb,*kcvf,*krb,*qcqr;
  cudaGetSymbolAddress((void**)&hs16, g_hs16);
  cudaGetSymbolAddress((void**)&wqkv, g_Wqkv);
  cudaGetSymbolAddress((void**)&wkv , g_Wkv);
  cudaGetSymbolAddress((void**)&wq  , g_Wq);
  cudaGetSymbolAddress((void**)&wrk , g_Wrk);
  cudaGetSymbolAddress((void**)&wob , g_Wob);
  cudaGetSymbolAddress((void**)&dA1 , g_dA1);
  cudaGetSymbolAddress((void**)&kcvf, g_kcvf);
  cudaGetSymbolAddress((void**)&qcqr, g_qcqr);
  cudaGetSymbolAddress((void**)&krb , g_krb);
  cudaGetSymbolAddress((void**)&qb  , g_qb);
  cudaGetSymbolAddress((void**)&kb  , g_kb);
  cudaGetSymbolAddress((void**)&vb  , g_vb);
  cudaGetSymbolAddress((void**)&at1 , g_at1);

  // --- input conversions ---
  convA_kernel<<<(TOKn*1536/4)/256, 256>>>((const float4*)hs, hs16);
  {
    ConvJobs J;
    const float* Ws[8] = {Wkvd, Wqd, Wku, Wvu, Wqu, Wrq, Wrk, Wo};
    __half* Bs[8] = {wqkv, wqkv + (size_t)192*1536, wkv,
                     wkv + (size_t)768*192, wq, wq + (size_t)768*192,
                     wrk, wob};
    int Ks[8]  = {1536,1536,192,192,192,192,1536,1536};
    int Nsz[8] = {192,192,768,1536,768,768,768,1536};
    int acc = 0;
    for (int j = 0; j < 8; j++) {
      J.W[j] = Ws[j]; J.Bt[j] = Bs[j];
      J.K[j] = Ks[j]; J.N[j] = Nsz[j];
      J.bstart[j] = acc;
      acc += (Nsz[j]/32)*(Ks[j]/32);
    }
    J.bstart[8] = acc;
    convW_kernel<<<acc, dim3(32,8)>>>(J);
  }

  // --- GEMM smem sizes ---
  const int SM_64  = (128 +  64)*72*2*3;  // 82944
  const int SM_128 = (128 + 128)*72*2*3;  // 110592
  cudaFuncSetAttribute(hgemm_kernel<64,1>,
      cudaFuncAttributeMaxDynamicSharedMemorySize, SM_64);
  cudaFuncSetAttribute(hgemm_kernel<128,3>,
      cudaFuncAttributeMaxDynamicSharedMemorySize, SM_128);

  // --- qkvd: dA1 = hs @ [Wkvd|Wqd]  (single-pass, fp16 out, BN=64) ---
  {
    GJobs J{};
    J.j[0] = {hs16, wqkv, nullptr, dA1, 1536, 384, 1536, 1, 6};
    J.bstart[0] = 0; J.bstart[1] = 192;
    hgemm_kernel<64,1><<<192, 256, SM_64>>>(J);
  }
  // --- batched single-pass: krb | kcvf | qcqr (all fp16 out) ---
  {
    GJobs J{};
    J.j[0] = {hs16,    wrk, nullptr, krb,  1536,  768, 1536, 1,  6};
    J.j[1] = {dA1,     wkv, nullptr, kcvf,  384, 2304,  192, 1, 18};
    J.j[2] = {dA1+192, wq,  nullptr, qcqr,  384, 1536,  192, 1, 12};
    J.bstart[0] = 0; J.bstart[1] = 192; J.bstart[2] = 768; J.bstart[3] = 1152;
    hgemm_kernel<128,3><<<1152, 256, SM_128>>>(J);
  }

  // rope + layout (coalesced)
  assemble_kernel<<<dim3(Sn, Bn), 256>>>(qcqr, kcvf, krb, rot, qb, kb, vb);

  // flash attention: paired q-tiles, perfectly balanced single wave
  cudaFuncSetAttribute(flash_kernel, cudaFuncAttributeMaxDynamicSharedMemorySize,
                       FLASH_SMEM);
  flash_kernel<<<dim3(Hn*Bn, 8), 256, FLASH_SMEM>>>(qb, kb, vb, at1);

  // --- output projection: BN=64 (768 blocks) ---
  {
    GJobs J{};
    J.j[0] = {at1, wob, out, nullptr, 1536, 1536, 1536, 0, 24};
    J.bstart[0] = 0; J.bstart[1] = 768;
    hgemm_kernel<64,1><<<768, 256, SM_64>>>(J);
  }
}

// round 16
// speedup vs baseline: 1.0678x; 1.0678x over previous
#include <cuda_runtime.h>
#include <cuda_fp16.h>
#include <cstdint>
#include <stdint.h>
#include <math.h>

#define Bn   2
#define Sn   2048
#define HIDn 1536
#define Hn   12
#define HDn  128
#define TOKn (Bn*Sn)   // 4096

// ---------------- scratch (device globals; no allocations allowed) ----------
__device__ __half g_hs16[(size_t)TOKn*1536];     // hidden single fp16
__device__ __half g_Wqkv[(size_t)384*1536];      // [n][k] single fp16
__device__ __half g_Wkv [(size_t)2304*192];
__device__ __half g_Wq  [(size_t)1536*192];
__device__ __half g_Wrk [(size_t)768*1536];
__device__ __half g_Wob [(size_t)1536*1536];
__device__ __half g_dA1 [(size_t)TOKn*384];      // [tok][kvd192|qd192] single fp16
__device__ __half g_kcvf[(size_t)TOKn*2304];     // fp16
__device__ __half g_qcqr[(size_t)TOKn*1536];     // fp16
__device__ __half g_krb [(size_t)TOKn*768];      // fp16
__device__ __half g_qb[(size_t)Bn*Hn*Sn*128];    // Q single fp16 (scaled)
__device__ __half g_kb[(size_t)Bn*Hn*Sn*128];    // K single
__device__ __half g_vb[(size_t)Bn*Hn*Sn*128];    // V single
__device__ __half g_at1[(size_t)TOKn*1536];      // attn out single fp16

// ---------------- helpers ----------------------------------------------------
__device__ __forceinline__ unsigned pack2h(float a, float b) {
  __half2 t = __floats2half2_rn(a, b);
  return *(unsigned*)&t;
}

#define MMAF16(d0,d1,d2,d3,a0,a1,a2,a3,b0,b1)                              \
  asm volatile("mma.sync.aligned.m16n8k16.row.col.f32.f16.f16.f32 "         \
    "{%0,%1,%2,%3},{%4,%5,%6,%7},{%8,%9},{%0,%1,%2,%3};"                    \
    : "+f"(d0),"+f"(d1),"+f"(d2),"+f"(d3)                                    \
    : "r"(a0),"r"(a1),"r"(a2),"r"(a3),"r"(b0),"r"(b1))
#define LDSM_X4(r0,r1,r2,r3,addr)                                           \
  asm volatile("ldmatrix.sync.aligned.m8n8.x4.shared.b16 "                  \
    "{%0,%1,%2,%3},[%4];"                                                   \
    : "=r"(r0),"=r"(r1),"=r"(r2),"=r"(r3) : "r"(addr))
#define LDSM_X4T(r0,r1,r2,r3,addr)                                          \
  asm volatile("ldmatrix.sync.aligned.m8n8.x4.trans.shared.b16 "            \
    "{%0,%1,%2,%3},[%4];"                                                   \
    : "=r"(r0),"=r"(r1),"=r"(r2),"=r"(r3) : "r"(addr))
#define CPASYNC16(dst, src)                                                 \
  asm volatile("cp.async.cg.shared.global [%0],[%1],16;" :: "r"(dst), "l"(src))

// ---------------- conversion kernels ----------------------------------------
__global__ __launch_bounds__(256)
void convA_kernel(const float4* __restrict__ X, __half* __restrict__ Y) {
  size_t i = (size_t)blockIdx.x*256 + threadIdx.x;
  float4 v = X[i];
  __half2 h0 = __floats2half2_rn(v.x, v.y);
  __half2 h1 = __floats2half2_rn(v.z, v.w);
  *(__half2*)(Y + i*4)     = h0;
  *(__half2*)(Y + i*4 + 2) = h1;
}

struct ConvJobs {
  const float* W[8];
  __half* Bt[8];
  int K[8], N[8];
  int bstart[9];
};
__global__ __launch_bounds__(256)
void convW_kernel(ConvJobs J) {
  __shared__ float t[32][33];
  int bx = blockIdx.x;
  int j = 0;
  while (bx >= J.bstart[j+1]) j++;
  int lb = bx - J.bstart[j];
  int nbn = J.N[j] >> 5;
  int n0 = (lb % nbn) << 5, k0 = (lb / nbn) << 5;
  const float* W = J.W[j];
  __half* Bt = J.Bt[j];
  int K = J.K[j], N = J.N[j];
  #pragma unroll
  for (int i = threadIdx.y; i < 32; i += 8)
    t[i][threadIdx.x] = W[(size_t)(k0+i)*N + n0 + threadIdx.x];
  __syncthreads();
  #pragma unroll
  for (int i = threadIdx.y; i < 32; i += 8) {
    int n = n0 + i, k = k0 + threadIdx.x;
    Bt[(size_t)n*K + k] = __float2half(t[threadIdx.x][i]);
  }
}

// ---------------- fp16 tensor-core GEMM (batched, 3-stage, BK=64) -----------
struct GJob {
  const __half *Am, *Bm;
  float* C; __half* Cb;
  int lda, N, K, outmode, nbx;
};
struct GJobs { GJob j[3]; int bstart[4]; };

template<int BN, int NJ>
__global__ __launch_bounds__(256)
void hgemm_kernel(GJobs JB) {
  constexpr int BOFF  = 128*72;
  constexpr int STAGE = (128 + BN)*72;
  constexpr int WN = BN/32, WM = 8/WN, MT = 128/(WM*16);

  extern __shared__ __half hsm[];
  int tid = threadIdx.x;
  int bid = blockIdx.x;
  int ji = 0;
  #pragma unroll
  for (int t = 1; t < NJ; t++) if (bid >= JB.bstart[t]) ji = t;
  GJob jb = JB.j[ji];
  int lb = bid - JB.bstart[ji];
  int bx = lb % jb.nbx, by = lb / jb.nbx;
  const __half* Am = jb.Am;
  const __half* Bm = jb.Bm;
  int lda = jb.lda, N = jb.N, K = jb.K;
  int KIT = K >> 6;

  auto load_st = [&](int it, int slot) {
    int kk = it << 6;
    __half* dst = hsm + slot*STAGE;
    #pragma unroll
    for (int p = 0; p < 4; p++) {
      int u = tid + (p << 8);
      int row = u >> 3, c = u & 7;
      size_t ga = (size_t)(by*128 + row)*lda + kk + c*8;
      unsigned dh = (unsigned)__cvta_generic_to_shared(dst + row*72 + c*8);
      CPASYNC16(dh, Am + ga);
    }
    #pragma unroll
    for (int p = 0; p < BN/32; p++) {
      int u = tid + (p << 8);
      int row = u >> 3, c = u & 7;
      const __half* sB = Bm + (size_t)(bx*BN + row)*K + kk + c*8;
      unsigned db = (unsigned)__cvta_generic_to_shared(dst + BOFF + row*72 + c*8);
      CPASYNC16(db, sB);
    }
    asm volatile("cp.async.commit_group;");
  };

  int wid = tid >> 5, lane = tid & 31;
  int wm = wid / WN, wn = wid % WN;
  int g = lane >> 2, tig = lane & 3;
  int lr = lane & 15, lc = (lane >> 4) << 3;

  float acc[MT][4][4];
  #pragma unroll
  for (int mt=0; mt<MT; mt++)
    #pragma unroll
    for (int nt=0; nt<4; nt++)
      #pragma unroll
      for (int r=0; r<4; r++) acc[mt][nt][r] = 0.f;

  load_st(0, 0);
  load_st(1, 1);

  for (int it = 0; it < KIT; ++it) {
    if (it + 1 < KIT) asm volatile("cp.async.wait_group 1;");
    else              asm volatile("cp.async.wait_group 0;");
    __syncthreads();
    if (it + 2 < KIT) load_st(it + 2, (it + 2) % 3);
    const __half* St = hsm + (it % 3)*STAGE;

    #pragma unroll
    for (int ks = 0; ks < 4; ks++) {
      unsigned b[4][2];
      #pragma unroll
      for (int bt = 0; bt < 2; bt++) {
        unsigned q0,q1,q2,q3;
        unsigned bd = (unsigned)__cvta_generic_to_shared(
            St + BOFF + (wn*32 + bt*16 + lr)*72 + ks*16 + lc);
        LDSM_X4(q0,q1,q2,q3, bd);
        b[2*bt  ][0] = q0; b[2*bt  ][1] = q2;
        b[2*bt+1][0] = q1; b[2*bt+1][1] = q3;
      }
      unsigned a[MT][4];
      #pragma unroll
      for (int mt = 0; mt < MT; mt++) {
        unsigned ad = (unsigned)__cvta_generic_to_shared(
            St + (wm*(MT*16) + mt*16 + lr)*72 + ks*16 + lc);
        LDSM_X4(a[mt][0], a[mt][1], a[mt][2], a[mt][3], ad);
      }
      #pragma unroll
      for (int mt = 0; mt < MT; mt++)
        #pragma unroll
        for (int nt = 0; nt < 4; nt++)
          MMAF16(acc[mt][nt][0],acc[mt][nt][1],acc[mt][nt][2],acc[mt][nt][3],
                 a[mt][0],a[mt][1],a[mt][2],a[mt][3],
                 b[nt][0],b[nt][1]);
    }
  }

  #pragma unroll
  for (int mt = 0; mt < MT; mt++) {
    #pragma unroll
    for (int nt = 0; nt < 4; nt++) {
      int row = by*128 + wm*(MT*16) + mt*16 + g;
      int col = bx*BN + wn*32 + nt*8 + 2*tig;
      if (jb.outmode == 0) {
        float2 v0 = make_float2(acc[mt][nt][0], acc[mt][nt][1]);
        float2 v1 = make_float2(acc[mt][nt][2], acc[mt][nt][3]);
        *(float2*)&jb.C[(size_t)row    *N + col] = v0;
        *(float2*)&jb.C[(size_t)(row+8)*N + col] = v1;
      } else {
        *(__half2*)&jb.Cb[(size_t)row    *N + col] =
            __floats2half2_rn(acc[mt][nt][0], acc[mt][nt][1]);
        *(__half2*)&jb.Cb[(size_t)(row+8)*N + col] =
            __floats2half2_rn(acc[mt][nt][2], acc[mt][nt][3]);
      }
    }
  }
}

// ---------------- assemble: RoPE + layout + scale (coalesced) ---------------
__global__ __launch_bounds__(256)
void assemble_kernel(const __half* __restrict__ qcqr, const __half* __restrict__ kcvf,
                     const __half* __restrict__ krb, const float* __restrict__ rot,
                     __half* __restrict__ Qh, __half* __restrict__ Kh,
                     __half* __restrict__ Vh) {
  int s = blockIdx.x, b = blockIdx.y;
  int tid = threadIdx.x;
  int token = b*Sn + s;
  const float* rrow = rot + (size_t)s*64;
  const float SCALE = 0.08838834764831845f * 1.4426950408889634f;

  #pragma unroll
  for (int it = 0; it < 6; it++) {
    int lin = it*256 + tid;
    int h = lin >> 7, d = lin & 127;
    size_t bhs = (size_t)(b*Hn + h)*Sn + s;

    Vh[bhs*128 + d] = kcvf[(size_t)token*2304 + 768 + h*HDn + d];

    float qv, kv;
    if (d < 64) {
      qv = __half2float(qcqr[(size_t)token*1536 + h*64 + d]);
      kv = __half2float(kcvf[(size_t)token*2304 + h*64 + d]);
    } else {
      int i = d - 64;
      const __half* qrow = qcqr + (size_t)token*1536 + 768 + h*64;
      const __half* krow = krb + (size_t)token*768 + h*64;
      if (i < 32) {
        float sn = rrow[i], cs = rrow[32+i];
        qv = __half2float(qrow[i])*cs - __half2float(qrow[i+32])*sn;
        kv = __half2float(krow[i])*cs - __half2float(krow[i+32])*sn;
      } else {
        int ii = i - 32;
        float sn = rrow[ii], cs = rrow[32+ii];
        qv = __half2float(qrow[ii])*sn + __half2float(qrow[ii+32])*cs;
        kv = __half2float(krow[ii])*sn + __half2float(krow[ii+32])*cs;
      }
    }
    Qh[bhs*128 + d] = __float2half(qv * SCALE);
    Kh[bhs*128 + d] = __float2half(kv);
  }
}

// ---------------- causal flash attention (QK 1-pass, PV 1-pass, exp2) -------
// grid (24 bh, 16 qtiles): qi is the SLOW dim -> longest blocks dispatch first.
#define FLASH_SMEM 104448

__global__ __launch_bounds__(256, 2)
void flash_kernel(const __half* __restrict__ Qg,
                  const __half* __restrict__ Kg,
                  const __half* __restrict__ Vg,
                  __half* __restrict__ At) {
  extern __shared__ __half fsm[];
  __half* Qs = fsm;              // [128][136]
  __half* Ks = fsm + 17408;      // [2 buf][64][136]
  __half* Vs = fsm + 34816;      // [2 buf][64][136]

  int bh = (int)blockIdx.x;          // 0..23
  int qi = 15 - (int)blockIdx.y;     // longest (qi=15) first
  int h = bh % Hn, b = bh / Hn;
  int qbase = qi*128;
  const __half* Qb = Qg + ((size_t)bh*Sn + qbase)*128;
  const __half* Kb = Kg + (size_t)bh*Sn*128;
  const __half* Vb = Vg + (size_t)bh*Sn*128;

  int tid = threadIdx.x;
  int wid = tid>>5, lane = tid&31, g = lane>>2, tig = lane&3;
  int lr = lane & 15, lc = (lane >> 4) << 3;
  int jmax = 2*qi + 2;
  int r0 = wid*16;

  #pragma unroll
  for (int p=0;p<8;p++){
    int lin = tid + p*256;
    int row = lin>>4, c = lin&15;
    const __half* src = Qb + (size_t)row*128 + c*8;
    unsigned d = (unsigned)__cvta_generic_to_shared(Qs + row*136 + c*8);
    CPASYNC16(d, src);
  }
  auto load_kv = [&](int jt, int buf){
    #pragma unroll
    for (int p=0;p<4;p++){
      int lin = tid + p*256;
      int row = lin>>4, c = lin&15;
      size_t s_off = (size_t)(jt*64 + row)*128 + c*8;
      int doff = buf*8704 + row*136 + c*8;
      unsigned dk = (unsigned)__cvta_generic_to_shared(Ks + doff);
      CPASYNC16(dk, Kb + s_off);
      unsigned dv = (unsigned)__cvta_generic_to_shared(Vs + doff);
      CPASYNC16(dv, Vb + s_off);
    }
    asm volatile("cp.async.commit_group;");
  };
  load_kv(0, 0);

  float o[16][4];
  #pragma unroll
  for (int nt=0;nt<16;nt++)
    #pragma unroll
    for (int r=0;r<4;r++) o[nt][r] = 0.f;
  float m0=-1e30f, m1=-1e30f, l0=0.f, l1=0.f;

  for (int jt = 0; jt < jmax; jt++) {
    int buf = jt & 1;
    asm volatile("cp.async.wait_group 0;");
    __syncthreads();
    if (jt + 1 < jmax) load_kv(jt+1, buf^1);

    const __half* Kbuf = Ks + buf*8704;
    float acc[8][4];
    #pragma unroll
    for (int t=0;t<8;t++)
      #pragma unroll
      for (int r=0;r<4;r++) acc[t][r] = 0.f;

    #pragma unroll
    for (int ks=0; ks<8; ks++){
      unsigned ah[4];
      {
        unsigned qd = (unsigned)__cvta_generic_to_shared(
            Qs + (r0 + lr)*136 + ks*16 + lc);
        LDSM_X4(ah[0],ah[1],ah[2],ah[3], qd);
      }
      unsigned bk[8][2];
      #pragma unroll
      for (int t16=0; t16<4; t16++){
        unsigned q0,q1,q2,q3;
        unsigned kd = (unsigned)__cvta_generic_to_shared(
            Kbuf + (t16*16 + lr)*136 + ks*16 + lc);
        LDSM_X4(q0,q1,q2,q3, kd);
        bk[2*t16  ][0] = q0; bk[2*t16  ][1] = q2;
        bk[2*t16+1][0] = q1; bk[2*t16+1][1] = q3;
      }
      #pragma unroll
      for (int t=0;t<8;t++)
        MMAF16(acc[t][0],acc[t][1],acc[t][2],acc[t][3],
               ah[0],ah[1],ah[2],ah[3], bk[t][0],bk[t][1]);
    }

    if (jt >= jmax-2) {
      int rg0 = qbase + r0 + g, rg1 = rg0 + 8;
      #pragma unroll
      for (int t=0;t<8;t++){
        int c0 = jt*64 + t*8 + 2*tig;
        if (c0   > rg0) acc[t][0] = -1e30f;
        if (c0+1 > rg0) acc[t][1] = -1e30f;
        if (c0   > rg1) acc[t][2] = -1e30f;
        if (c0+1 > rg1) acc[t][3] = -1e30f;
      }
    }

    float mx0=-1e30f, mx1=-1e30f;
    #pragma unroll
    for (int t=0;t<8;t++){
      mx0 = fmaxf(mx0, fmaxf(acc[t][0],acc[t][1]));
      mx1 = fmaxf(mx1, fmaxf(acc[t][2],acc[t][3]));
    }
    mx0 = fmaxf(mx0, __shfl_xor_sync(0xffffffffu, mx0, 1));
    mx0 = fmaxf(mx0, __shfl_xor_sync(0xffffffffu, mx0, 2));
    mx1 = fmaxf(mx1, __shfl_xor_sync(0xffffffffu, mx1, 1));
    mx1 = fmaxf(mx1, __shfl_xor_sync(0xffffffffu, mx1, 2));
    float nm0 = fmaxf(m0, mx0), nm1 = fmaxf(m1, mx1);
    float cf0 = exp2f(m0 - nm0), cf1 = exp2f(m1 - nm1);
    m0 = nm0; m1 = nm1;
    float s0 = 0.f, s1 = 0.f;
    #pragma unroll
    for (int t=0;t<8;t++){
      acc[t][0] = exp2f(acc[t][0]-nm0);
      acc[t][1] = exp2f(acc[t][1]-nm0);
      acc[t][2] = exp2f(acc[t][2]-nm1);
      acc[t][3] = exp2f(acc[t][3]-nm1);
      s0 += acc[t][0]+acc[t][1];
      s1 += acc[t][2]+acc[t][3];
    }
    s0 += __shfl_xor_sync(0xffffffffu, s0, 1);
    s0 += __shfl_xor_sync(0xffffffffu, s0, 2);
    s1 += __shfl_xor_sync(0xffffffffu, s1, 1);
    s1 += __shfl_xor_sync(0xffffffffu, s1, 2);
    l0 = l0*cf0 + s0;
    l1 = l1*cf1 + s1;
    #pragma unroll
    for (int nt=0;nt<16;nt++){
      o[nt][0] *= cf0; o[nt][1] *= cf0;
      o[nt][2] *= cf1; o[nt][3] *= cf1;
    }

    const __half* Vbuf = Vs + buf*8704;
    int vrow = ((lane>>3)&1)*8 + (lane&7);
    int vcol = (lane>>4)*8;
    #pragma unroll
    for (int u=0;u<4;u++){
      unsigned ph[4];
      ph[0] = pack2h(acc[2*u  ][0], acc[2*u  ][1]);
      ph[1] = pack2h(acc[2*u  ][2], acc[2*u  ][3]);
      ph[2] = pack2h(acc[2*u+1][0], acc[2*u+1][1]);
      ph[3] = pack2h(acc[2*u+1][2], acc[2*u+1][3]);
      unsigned base = (unsigned)__cvta_generic_to_shared(
          Vbuf + (u*16 + vrow)*136 + vcol);
      #pragma unroll
      for (int dt=0;dt<8;dt++){
        unsigned v0,v1,v2,v3;
        LDSM_X4T(v0,v1,v2,v3, base + dt*32);
        MMAF16(o[dt*2  ][0],o[dt*2  ][1],o[dt*2  ][2],o[dt*2  ][3],
               ph[0],ph[1],ph[2],ph[3], v0,v1);
        MMAF16(o[dt*2+1][0],o[dt*2+1][1],o[dt*2+1][2],o[dt*2+1][3],
               ph[0],ph[1],ph[2],ph[3], v2,v3);
      }
    }
  }

  float i0 = 1.f/l0, i1 = 1.f/l1;
  int tok0 = b*Sn + qbase + r0 + g;
  __half* o0 = At + (size_t)tok0*1536 + h*128;
  __half* o1 = At + (size_t)(tok0+8)*1536 + h*128;
  #pragma unroll
  for (int nt=0;nt<16;nt++){
    int col = nt*8 + 2*tig;
    *(__half2*)(o0 + col) = __floats2half2_rn(o[nt][0]*i0, o[nt][1]*i0);
    *(__half2*)(o1 + col) = __floats2half2_rn(o[nt][2]*i1, o[nt][3]*i1);
  }
}

// ---------------- launch -----------------------------------------------------
extern "C" void kernel_launch(void* const* d_in, const int* in_sizes, int n_in,
                              void* d_out, int out_size) {
  (void)in_sizes; (void)n_in; (void)out_size;
  const float* hs   = (const float*)d_in[0];
  const float* rot  = (const float*)d_in[1];
  const float* Wkvd = (const float*)d_in[2];
  const float* Wqd  = (const float*)d_in[3];
  const float* Wku  = (const float*)d_in[4];
  const float* Wqu  = (const float*)d_in[5];
  const float* Wvu  = (const float*)d_in[6];
  const float* Wrk  = (const float*)d_in[7];
  const float* Wrq  = (const float*)d_in[8];
  const float* Wo   = (const float*)d_in[9];
  float* out = (float*)d_out;

  __half *hs16,*wqkv,*wkv,*wq,*wrk,*wob,*dA1,*at1,*qb,*kb,*vb,*kcvf,*krb,*qcqr;
  cudaGetSymbolAddress((void**)&hs16, g_hs16);
  cudaGetSymbolAddress((void**)&wqkv, g_Wqkv);
  cudaGetSymbolAddress((void**)&wkv , g_Wkv);
  cudaGetSymbolAddress((void**)&wq  , g_Wq);
  cudaGetSymbolAddress((void**)&wrk , g_Wrk);
  cudaGetSymbolAddress((void**)&wob , g_Wob);
  cudaGetSymbolAddress((void**)&dA1 , g_dA1);
  cudaGetSymbolAddress((void**)&kcvf, g_kcvf);
  cudaGetSymbolAddress((void**)&qcqr, g_qcqr);
  cudaGetSymbolAddress((void**)&krb , g_krb);
  cudaGetSymbolAddress((void**)&qb  , g_qb);
  cudaGetSymbolAddress((void**)&kb  , g_kb);
  cudaGetSymbolAddress((void**)&vb  , g_vb);
  cudaGetSymbolAddress((void**)&at1 , g_at1);

  // --- input conversions ---
  convA_kernel<<<(TOKn*1536/4)/256, 256>>>((const float4*)hs, hs16);
  {
    ConvJobs J;
    const float* Ws[8] = {Wkvd, Wqd, Wku, Wvu, Wqu, Wrq, Wrk, Wo};
    __half* Bs[8] = {wqkv, wqkv + (size_t)192*1536, wkv,
                     wkv + (size_t)768*192, wq, wq + (size_t)768*192,
                     wrk, wob};
    int Ks[8]  = {1536,1536,192,192,192,192,1536,1536};
    int Nsz[8] = {192,192,768,1536,768,768,768,1536};
    int acc = 0;
    for (int j = 0; j < 8; j++) {
      J.W[j] = Ws[j]; J.Bt[j] = Bs[j];
      J.K[j] = Ks[j]; J.N[j] = Nsz[j];
      J.bstart[j] = acc;
      acc += (Nsz[j]/32)*(Ks[j]/32);
    }
    J.bstart[8] = acc;
    convW_kernel<<<acc, dim3(32,8)>>>(J);
  }

  // --- GEMM smem sizes ---
  const int SM_64  = (128 +  64)*72*2*3;  // 82944
  const int SM_128 = (128 + 128)*72*2*3;  // 110592
  cudaFuncSetAttribute(hgemm_kernel<64,2>,
      cudaFuncAttributeMaxDynamicSharedMemorySize, SM_64);
  cudaFuncSetAttribute(hgemm_kernel<128,2>,
      cudaFuncAttributeMaxDynamicSharedMemorySize, SM_128);
  cudaFuncSetAttribute(hgemm_kernel<64,1>,
      cudaFuncAttributeMaxDynamicSharedMemorySize, SM_64);

  // --- launch 1: qkvd + krb (both depend only on hs16) -> 576 blocks ---
  {
    GJobs J{};
    J.j[0] = {hs16, wqkv, nullptr, dA1, 1536,  384, 1536, 1,  6};
    J.j[1] = {hs16, wrk,  nullptr, krb, 1536,  768, 1536, 1, 12};
    J.bstart[0] = 0; J.bstart[1] = 192; J.bstart[2] = 576;
    hgemm_kernel<64,2><<<576, 256, SM_64>>>(J);
  }
  // --- launch 2: kcvf | qcqr (depend on dA1) -> 960 blocks ---
  {
    GJobs J{};
    J.j[0] = {dA1,     wkv, nullptr, kcvf, 384, 2304, 192, 1, 18};
    J.j[1] = {dA1+192, wq,  nullptr, qcqr, 384, 1536, 192, 1, 12};
    J.bstart[0] = 0; J.bstart[1] = 576; J.bstart[2] = 960;
    hgemm_kernel<128,2><<<960, 256, SM_128>>>(J);
  }

  // rope + layout (coalesced)
  assemble_kernel<<<dim3(Sn, Bn), 256>>>(qcqr, kcvf, krb, rot, qb, kb, vb);

  // flash attention: qi slowest -> LPT dispatch order (R14 config)
  cudaFuncSetAttribute(flash_kernel, cudaFuncAttributeMaxDynamicSharedMemorySize,
                       FLASH_SMEM);
  flash_kernel<<<dim3(Hn*Bn, 16), 256, FLASH_SMEM>>>(qb, kb, vb, at1);

  // --- output projection: BN=64 (768 blocks) ---
  {
    GJobs J{};
    J.j[0] = {at1, wob, out, nullptr, 1536, 1536, 1536, 0, 24};
    J.bstart[0] = 0; J.bstart[1] = 768;
    hgemm_kernel<64,1><<<768, 256, SM_64>>>(J);
  }
}

// round 17
// speedup vs baseline: 1.1265x; 1.0550x over previous
#include <cuda_runtime.h>
#include <cuda_fp16.h>
#include <cstdint>
#include <stdint.h>
#include <math.h>

#define Bn   2
#define Sn   2048
#define HIDn 1536
#define Hn   12
#define HDn  128
#define TOKn (Bn*Sn)   // 4096
#define QSCALE (0.08838834764831845f * 1.4426950408889634f)

// ---------------- scratch (device globals; no allocations allowed) ----------
__device__ __half g_hs16[(size_t)TOKn*1536];     // hidden single fp16
__device__ __half g_Wqkv[(size_t)384*1536];      // [n][k] single fp16
__device__ __half g_Wkv [(size_t)2304*192];      // [Wku 768 | Wvu 1536] rows
__device__ __half g_Wq  [(size_t)1536*192];      // [Wqu 768 | Wrq 768] rows
__device__ __half g_Wrk [(size_t)768*1536];
__device__ __half g_Wob [(size_t)1536*1536];
__device__ __half g_dA1 [(size_t)TOKn*384];      // [tok][kvd192|qd192]
__device__ __half g_qr  [(size_t)TOKn*768];      // q_rope pre-scaled fp16
__device__ __half g_krb [(size_t)TOKn*768];      // k_rope fp16
__device__ __half g_qb[(size_t)Bn*Hn*Sn*128];    // Q (scaled)
__device__ __half g_kb[(size_t)Bn*Hn*Sn*128];    // K
__device__ __half g_vb[(size_t)Bn*Hn*Sn*128];    // V
__device__ __half g_at1[(size_t)TOKn*1536];      // attn out fp16

// ---------------- helpers ----------------------------------------------------
__device__ __forceinline__ unsigned pack2h(float a, float b) {
  __half2 t = __floats2half2_rn(a, b);
  return *(unsigned*)&t;
}

#define MMAF16(d0,d1,d2,d3,a0,a1,a2,a3,b0,b1)                              \
  asm volatile("mma.sync.aligned.m16n8k16.row.col.f32.f16.f16.f32 "         \
    "{%0,%1,%2,%3},{%4,%5,%6,%7},{%8,%9},{%0,%1,%2,%3};"                    \
    : "+f"(d0),"+f"(d1),"+f"(d2),"+f"(d3)                                    \
    : "r"(a0),"r"(a1),"r"(a2),"r"(a3),"r"(b0),"r"(b1))
#define LDSM_X4(r0,r1,r2,r3,addr)                                           \
  asm volatile("ldmatrix.sync.aligned.m8n8.x4.shared.b16 "                  \
    "{%0,%1,%2,%3},[%4];"                                                   \
    : "=r"(r0),"=r"(r1),"=r"(r2),"=r"(r3) : "r"(addr))
#define LDSM_X4T(r0,r1,r2,r3,addr)                                          \
  asm volatile("ldmatrix.sync.aligned.m8n8.x4.trans.shared.b16 "            \
    "{%0,%1,%2,%3},[%4];"                                                   \
    : "=r"(r0),"=r"(r1),"=r"(r2),"=r"(r3) : "r"(addr))
#define CPASYNC16(dst, src)                                                 \
  asm volatile("cp.async.cg.shared.global [%0],[%1],16;" :: "r"(dst), "l"(src))

// ---------------- conversion kernels ----------------------------------------
__global__ __launch_bounds__(256)
void convA_kernel(const float4* __restrict__ X, __half* __restrict__ Y) {
  size_t i = (size_t)blockIdx.x*256 + threadIdx.x;
  float4 v = X[i];
  __half2 h0 = __floats2half2_rn(v.x, v.y);
  __half2 h1 = __floats2half2_rn(v.z, v.w);
  *(__half2*)(Y + i*4)     = h0;
  *(__half2*)(Y + i*4 + 2) = h1;
}

struct ConvJobs {
  const float* W[8];
  __half* Bt[8];
  int K[8], N[8];
  int bstart[9];
};
__global__ __launch_bounds__(256)
void convW_kernel(ConvJobs J) {
  __shared__ float t[32][33];
  int bx = blockIdx.x;
  int j = 0;
  while (bx >= J.bstart[j+1]) j++;
  int lb = bx - J.bstart[j];
  int nbn = J.N[j] >> 5;
  int n0 = (lb % nbn) << 5, k0 = (lb / nbn) << 5;
  const float* W = J.W[j];
  __half* Bt = J.Bt[j];
  int K = J.K[j], N = J.N[j];
  #pragma unroll
  for (int i = threadIdx.y; i < 32; i += 8)
    t[i][threadIdx.x] = W[(size_t)(k0+i)*N + n0 + threadIdx.x];
  __syncthreads();
  #pragma unroll
  for (int i = threadIdx.y; i < 32; i += 8) {
    int n = n0 + i, k = k0 + threadIdx.x;
    Bt[(size_t)n*K + k] = __float2half(t[threadIdx.x][i]);
  }
}

// ---------------- fp16 tensor-core GEMM (batched, 3-stage, BK=64) -----------
// outmode: 0 fp32 linear | 1 fp16 linear | 2 scatter kb lower-64 |
//          3 scatter vb 128-d | 4 scatter qb lower-64 *QSCALE | 5 fp16 linear *QSCALE
struct GJob {
  const __half *Am, *Bm;
  float* C; __half* Cb;
  int lda, N, K, outmode, nbx;
};
struct GJobs { GJob j[4]; int bstart[5]; };

template<int BN, int NJ>
__global__ __launch_bounds__(256)
void hgemm_kernel(GJobs JB) {
  constexpr int BOFF  = 128*72;
  constexpr int STAGE = (128 + BN)*72;
  constexpr int WN = BN/32, WM = 8/WN, MT = 128/(WM*16);

  extern __shared__ __half hsm[];
  int tid = threadIdx.x;
  int bid = blockIdx.x;
  int ji = 0;
  #pragma unroll
  for (int t = 1; t < NJ; t++) if (bid >= JB.bstart[t]) ji = t;
  GJob jb = JB.j[ji];
  int lb = bid - JB.bstart[ji];
  int bx = lb % jb.nbx, by = lb / jb.nbx;
  const __half* Am = jb.Am;
  const __half* Bm = jb.Bm;
  int lda = jb.lda, N = jb.N, K = jb.K;
  int KIT = K >> 6;

  auto load_st = [&](int it, int slot) {
    int kk = it << 6;
    __half* dst = hsm + slot*STAGE;
    #pragma unroll
    for (int p = 0; p < 4; p++) {
      int u = tid + (p << 8);
      int row = u >> 3, c = u & 7;
      size_t ga = (size_t)(by*128 + row)*lda + kk + c*8;
      unsigned dh = (unsigned)__cvta_generic_to_shared(dst + row*72 + c*8);
      CPASYNC16(dh, Am + ga);
    }
    #pragma unroll
    for (int p = 0; p < BN/32; p++) {
      int u = tid + (p << 8);
      int row = u >> 3, c = u & 7;
      const __half* sB = Bm + (size_t)(bx*BN + row)*K + kk + c*8;
      unsigned db = (unsigned)__cvta_generic_to_shared(dst + BOFF + row*72 + c*8);
      CPASYNC16(db, sB);
    }
    asm volatile("cp.async.commit_group;");
  };

  int wid = tid >> 5, lane = tid & 31;
  int wm = wid / WN, wn = wid % WN;
  int g = lane >> 2, tig = lane & 3;
  int lr = lane & 15, lc = (lane >> 4) << 3;

  float acc[MT][4][4];
  #pragma unroll
  for (int mt=0; mt<MT; mt++)
    #pragma unroll
    for (int nt=0; nt<4; nt++)
      #pragma unroll
      for (int r=0; r<4; r++) acc[mt][nt][r] = 0.f;

  load_st(0, 0);
  load_st(1, 1);

  for (int it = 0; it < KIT; ++it) {
    if (it + 1 < KIT) asm volatile("cp.async.wait_group 1;");
    else              asm volatile("cp.async.wait_group 0;");
    __syncthreads();
    if (it + 2 < KIT) load_st(it + 2, (it + 2) % 3);
    const __half* St = hsm + (it % 3)*STAGE;

    #pragma unroll
    for (int ks = 0; ks < 4; ks++) {
      unsigned b[4][2];
      #pragma unroll
      for (int bt = 0; bt < 2; bt++) {
        unsigned q0,q1,q2,q3;
        unsigned bd = (unsigned)__cvta_generic_to_shared(
            St + BOFF + (wn*32 + bt*16 + lr)*72 + ks*16 + lc);
        LDSM_X4(q0,q1,q2,q3, bd);
        b[2*bt  ][0] = q0; b[2*bt  ][1] = q2;
        b[2*bt+1][0] = q1; b[2*bt+1][1] = q3;
      }
      unsigned a[MT][4];
      #pragma unroll
      for (int mt = 0; mt < MT; mt++) {
        unsigned ad = (unsigned)__cvta_generic_to_shared(
            St + (wm*(MT*16) + mt*16 + lr)*72 + ks*16 + lc);
        LDSM_X4(a[mt][0], a[mt][1], a[mt][2], a[mt][3], ad);
      }
      #pragma unroll
      for (int mt = 0; mt < MT; mt++)
        #pragma unroll
        for (int nt = 0; nt < 4; nt++)
          MMAF16(acc[mt][nt][0],acc[mt][nt][1],acc[mt][nt][2],acc[mt][nt][3],
                 a[mt][0],a[mt][1],a[mt][2],a[mt][3],
                 b[nt][0],b[nt][1]);
    }
  }

  #pragma unroll
  for (int mt = 0; mt < MT; mt++) {
    #pragma unroll
    for (int nt = 0; nt < 4; nt++) {
      int row = by*128 + wm*(MT*16) + mt*16 + g;
      int col = bx*BN + wn*32 + nt*8 + 2*tig;
      float a0 = acc[mt][nt][0], a1 = acc[mt][nt][1];
      float a2 = acc[mt][nt][2], a3 = acc[mt][nt][3];
      int m = jb.outmode;
      if (m == 0) {
        *(float2*)&jb.C[(size_t)row    *N + col] = make_float2(a0, a1);
        *(float2*)&jb.C[(size_t)(row+8)*N + col] = make_float2(a2, a3);
      } else if (m == 1) {
        *(__half2*)&jb.Cb[(size_t)row    *N + col] = __floats2half2_rn(a0, a1);
        *(__half2*)&jb.Cb[(size_t)(row+8)*N + col] = __floats2half2_rn(a2, a3);
      } else if (m == 5) {
        *(__half2*)&jb.Cb[(size_t)row    *N + col] =
            __floats2half2_rn(a0*QSCALE, a1*QSCALE);
        *(__half2*)&jb.Cb[(size_t)(row+8)*N + col] =
            __floats2half2_rn(a2*QSCALE, a3*QSCALE);
      } else {
        float sc = (m == 4) ? QSCALE : 1.f;
        int b_ = row >> 11, s_ = row & 2047;
        int h_, d_;
        if (m == 3) { h_ = col >> 7; d_ = col & 127; }
        else        { h_ = col >> 6; d_ = col & 63;  }
        __half* base = jb.Cb + ((size_t)(b_*Hn + h_)*Sn + s_)*128 + d_;
        *(__half2*)base          = __floats2half2_rn(a0*sc, a1*sc);
        *(__half2*)(base + 8*128) = __floats2half2_rn(a2*sc, a3*sc);
      }
    }
  }
}

// ---------------- assemble: RoPE only (upper 64 dims of q,k) ----------------
__global__ __launch_bounds__(256)
void assemble_kernel(const __half* __restrict__ qr, const __half* __restrict__ krb,
                     const float* __restrict__ rot,
                     __half* __restrict__ Qh, __half* __restrict__ Kh) {
  int s = blockIdx.x, b = blockIdx.y;
  int tid = threadIdx.x;
  int token = b*Sn + s;
  const float* rrow = rot + (size_t)s*64;

  #pragma unroll
  for (int it = 0; it < 3; it++) {
    int lin = it*256 + tid;           // 0..767
    int h = lin >> 6, i = lin & 63;
    size_t bhs = (size_t)(b*Hn + h)*Sn + s;
    const __half* qrow = qr  + (size_t)token*768 + h*64;
    const __half* krow = krb + (size_t)token*768 + h*64;
    float qv, kv;
    if (i < 32) {
      float sn = rrow[i], cs = rrow[32+i];
      qv = __half2float(qrow[i])*cs - __half2float(qrow[i+32])*sn;
      kv = __half2float(krow[i])*cs - __half2float(krow[i+32])*sn;
    } else {
      int ii = i - 32;
      float sn = rrow[ii], cs = rrow[32+ii];
      qv = __half2float(qrow[ii])*sn + __half2float(qrow[ii+32])*cs;
      kv = __half2float(krow[ii])*sn + __half2float(krow[ii+32])*cs;
    }
    Qh[bhs*128 + 64 + i] = __float2half(qv);   // qr pre-scaled
    Kh[bhs*128 + 64 + i] = __float2half(kv);
  }
}

// ---------------- causal flash attention (QK 1-pass, PV 1-pass, exp2) -------
// grid (24 bh, 16 qtiles): qi slow -> LPT dispatch.
#define FLASH_SMEM 104448

__global__ __launch_bounds__(256, 2)
void flash_kernel(const __half* __restrict__ Qg,
                  const __half* __restrict__ Kg,
                  const __half* __restrict__ Vg,
                  __half* __restrict__ At) {
  extern __shared__ __half fsm[];
  __half* Qs = fsm;              // [128][136]
  __half* Ks = fsm + 17408;      // [2 buf][64][136]
  __half* Vs = fsm + 34816;      // [2 buf][64][136]

  int bh = (int)blockIdx.x;
  int qi = 15 - (int)blockIdx.y;
  int h = bh % Hn, b = bh / Hn;
  int qbase = qi*128;
  const __half* Qb = Qg + ((size_t)bh*Sn + qbase)*128;
  const __half* Kb = Kg + (size_t)bh*Sn*128;
  const __half* Vb = Vg + (size_t)bh*Sn*128;

  int tid = threadIdx.x;
  int wid = tid>>5, lane = tid&31, g = lane>>2, tig = lane&3;
  int lr = lane & 15, lc = (lane >> 4) << 3;
  int jmax = 2*qi + 2;
  int r0 = wid*16;

  #pragma unroll
  for (int p=0;p<8;p++){
    int lin = tid + p*256;
    int row = lin>>4, c = lin&15;
    const __half* src = Qb + (size_t)row*128 + c*8;
    unsigned d = (unsigned)__cvta_generic_to_shared(Qs + row*136 + c*8);
    CPASYNC16(d, src);
  }
  auto load_kv = [&](int jt, int buf){
    #pragma unroll
    for (int p=0;p<4;p++){
      int lin = tid + p*256;
      int row = lin>>4, c = lin&15;
      size_t s_off = (size_t)(jt*64 + row)*128 + c*8;
      int doff = buf*8704 + row*136 + c*8;
      unsigned dk = (unsigned)__cvta_generic_to_shared(Ks + doff);
      CPASYNC16(dk, Kb + s_off);
      unsigned dv = (unsigned)__cvta_generic_to_shared(Vs + doff);
      CPASYNC16(dv, Vb + s_off);
    }
    asm volatile("cp.async.commit_group;");
  };
  load_kv(0, 0);

  float o[16][4];
  #pragma unroll
  for (int nt=0;nt<16;nt++)
    #pragma unroll
    for (int r=0;r<4;r++) o[nt][r] = 0.f;
  float m0=-1e30f, m1=-1e30f, l0=0.f, l1=0.f;

  for (int jt = 0; jt < jmax; jt++) {
    int buf = jt & 1;
    asm volatile("cp.async.wait_group 0;");
    __syncthreads();
    if (jt + 1 < jmax) load_kv(jt+1, buf^1);

    const __half* Kbuf = Ks + buf*8704;
    float acc[8][4];
    #pragma unroll
    for (int t=0;t<8;t++)
      #pragma unroll
      for (int r=0;r<4;r++) acc[t][r] = 0.f;

    #pragma unroll
    for (int ks=0; ks<8; ks++){
      unsigned ah[4];
      {
        unsigned qd = (unsigned)__cvta_generic_to_shared(
            Qs + (r0 + lr)*136 + ks*16 + lc);
        LDSM_X4(ah[0],ah[1],ah[2],ah[3], qd);
      }
      unsigned bk[8][2];
      #pragma unroll
      for (int t16=0; t16<4; t16++){
        unsigned q0,q1,q2,q3;
        unsigned kd = (unsigned)__cvta_generic_to_shared(
            Kbuf + (t16*16 + lr)*136 + ks*16 + lc);
        LDSM_X4(q0,q1,q2,q3, kd);
        bk[2*t16  ][0] = q0; bk[2*t16  ][1] = q2;
        bk[2*t16+1][0] = q1; bk[2*t16+1][1] = q3;
      }
      #pragma unroll
      for (int t=0;t<8;t++)
        MMAF16(acc[t][0],acc[t][1],acc[t][2],acc[t][3],
               ah[0],ah[1],ah[2],ah[3], bk[t][0],bk[t][1]);
    }

    if (jt >= jmax-2) {
      int rg0 = qbase + r0 + g, rg1 = rg0 + 8;
      #pragma unroll
      for (int t=0;t<8;t++){
        int c0 = jt*64 + t*8 + 2*tig;
        if (c0   > rg0) acc[t][0] = -1e30f;
        if (c0+1 > rg0) acc[t][1] = -1e30f;
        if (c0   > rg1) acc[t][2] = -1e30f;
        if (c0+1 > rg1) acc[t][3] = -1e30f;
      }
    }

    float mx0=-1e30f, mx1=-1e30f;
    #pragma unroll
    for (int t=0;t<8;t++){
      mx0 = fmaxf(mx0, fmaxf(acc[t][0],acc[t][1]));
      mx1 = fmaxf(mx1, fmaxf(acc[t][2],acc[t][3]));
    }
    mx0 = fmaxf(mx0, __shfl_xor_sync(0xffffffffu, mx0, 1));
    mx0 = fmaxf(mx0, __shfl_xor_sync(0xffffffffu, mx0, 2));
    mx1 = fmaxf(mx1, __shfl_xor_sync(0xffffffffu, mx1, 1));
    mx1 = fmaxf(mx1, __shfl_xor_sync(0xffffffffu, mx1, 2));
    float nm0 = fmaxf(m0, mx0), nm1 = fmaxf(m1, mx1);
    float cf0 = exp2f(m0 - nm0), cf1 = exp2f(m1 - nm1);
    m0 = nm0; m1 = nm1;
    float s0 = 0.f, s1 = 0.f;
    #pragma unroll
    for (int t=0;t<8;t++){
      acc[t][0] = exp2f(acc[t][0]-nm0);
      acc[t][1] = exp2f(acc[t][1]-nm0);
      acc[t][2] = exp2f(acc[t][2]-nm1);
      acc[t][3] = exp2f(acc[t][3]-nm1);
      s0 += acc[t][0]+acc[t][1];
      s1 += acc[t][2]+acc[t][3];
    }
    s0 += __shfl_xor_sync(0xffffffffu, s0, 1);
    s0 += __shfl_xor_sync(0xffffffffu, s0, 2);
    s1 += __shfl_xor_sync(0xffffffffu, s1, 1);
    s1 += __shfl_xor_sync(0xffffffffu, s1, 2);
    l0 = l0*cf0 + s0;
    l1 = l1*cf1 + s1;
    #pragma unroll
    for (int nt=0;nt<16;nt++){
      o[nt][0] *= cf0; o[nt][1] *= cf0;
      o[nt][2] *= cf1; o[nt][3] *= cf1;
    }

    const __half* Vbuf = Vs + buf*8704;
    int vrow = ((lane>>3)&1)*8 + (lane&7);
    int vcol = (lane>>4)*8;
    #pragma unroll
    for (int u=0;u<4;u++){
      unsigned ph[4];
      ph[0] = pack2h(acc[2*u  ][0], acc[2*u  ][1]);
      ph[1] = pack2h(acc[2*u  ][2], acc[2*u  ][3]);
      ph[2] = pack2h(acc[2*u+1][0], acc[2*u+1][1]);
      ph[3] = pack2h(acc[2*u+1][2], acc[2*u+1][3]);
      unsigned base = (unsigned)__cvta_generic_to_shared(
          Vbuf + (u*16 + vrow)*136 + vcol);
      #pragma unroll
      for (int dt=0;dt<8;dt++){
        unsigned v0,v1,v2,v3;
        LDSM_X4T(v0,v1,v2,v3, base + dt*32);
        MMAF16(o[dt*2  ][0],o[dt*2  ][1],o[dt*2  ][2],o[dt*2  ][3],
               ph[0],ph[1],ph[2],ph[3], v0,v1);
        MMAF16(o[dt*2+1][0],o[dt*2+1][1],o[dt*2+1][2],o[dt*2+1][3],
               ph[0],ph[1],ph[2],ph[3], v2,v3);
      }
    }
  }

  float i0 = 1.f/l0, i1 = 1.f/l1;
  int tok0 = b*Sn + qbase + r0 + g;
  __half* o0 = At + (size_t)tok0*1536 + h*128;
  __half* o1 = At + (size_t)(tok0+8)*1536 + h*128;
  #pragma unroll
  for (int nt=0;nt<16;nt++){
    int col = nt*8 + 2*tig;
    *(__half2*)(o0 + col) = __floats2half2_rn(o[nt][0]*i0, o[nt][1]*i0);
    *(__half2*)(o1 + col) = __floats2half2_rn(o[nt][2]*i1, o[nt][3]*i1);
  }
}

// ---------------- launch -----------------------------------------------------
extern "C" void kernel_launch(void* const* d_in, const int* in_sizes, int n_in,
                              void* d_out, int out_size) {
  (void)in_sizes; (void)n_in; (void)out_size;
  const float* hs   = (const float*)d_in[0];
  const float* rot  = (const float*)d_in[1];
  const float* Wkvd = (const float*)d_in[2];
  const float* Wqd  = (const float*)d_in[3];
  const float* Wku  = (const float*)d_in[4];
  const float* Wqu  = (const float*)d_in[5];
  const float* Wvu  = (const float*)d_in[6];
  const float* Wrk  = (const float*)d_in[7];
  const float* Wrq  = (const float*)d_in[8];
  const float* Wo   = (const float*)d_in[9];
  float* out = (float*)d_out;

  __half *hs16,*wqkv,*wkv,*wq,*wrk,*wob,*dA1,*at1,*qb,*kb,*vb,*qr,*krb;
  cudaGetSymbolAddress((void**)&hs16, g_hs16);
  cudaGetSymbolAddress((void**)&wqkv, g_Wqkv);
  cudaGetSymbolAddress((void**)&wkv , g_Wkv);
  cudaGetSymbolAddress((void**)&wq  , g_Wq);
  cudaGetSymbolAddress((void**)&wrk , g_Wrk);
  cudaGetSymbolAddress((void**)&wob , g_Wob);
  cudaGetSymbolAddress((void**)&dA1 , g_dA1);
  cudaGetSymbolAddress((void**)&qr  , g_qr);
  cudaGetSymbolAddress((void**)&krb , g_krb);
  cudaGetSymbolAddress((void**)&qb  , g_qb);
  cudaGetSymbolAddress((void**)&kb  , g_kb);
  cudaGetSymbolAddress((void**)&vb  , g_vb);
  cudaGetSymbolAddress((void**)&at1 , g_at1);

  // --- input conversions ---
  convA_kernel<<<(TOKn*1536/4)/256, 256>>>((const float4*)hs, hs16);
  {
    ConvJobs J;
    const float* Ws[8] = {Wkvd, Wqd, Wku, Wvu, Wqu, Wrq, Wrk, Wo};
    __half* Bs[8] = {wqkv, wqkv + (size_t)192*1536, wkv,
                     wkv + (size_t)768*192, wq, wq + (size_t)768*192,
                     wrk, wob};
    int Ks[8]  = {1536,1536,192,192,192,192,1536,1536};
    int Nsz[8] = {192,192,768,1536,768,768,768,1536};
    int acc = 0;
    for (int j = 0; j < 8; j++) {
      J.W[j] = Ws[j]; J.Bt[j] = Bs[j];
      J.K[j] = Ks[j]; J.N[j] = Nsz[j];
      J.bstart[j] = acc;
      acc += (Nsz[j]/32)*(Ks[j]/32);
    }
    J.bstart[8] = acc;
    convW_kernel<<<acc, dim3(32,8)>>>(J);
  }

  // --- GEMM smem sizes ---
  const int SM_64  = (128 +  64)*72*2*3;  // 82944
  const int SM_128 = (128 + 128)*72*2*3;  // 110592
  cudaFuncSetAttribute(hgemm_kernel<64,2>,
      cudaFuncAttributeMaxDynamicSharedMemorySize, SM_64);
  cudaFuncSetAttribute(hgemm_kernel<128,4>,
      cudaFuncAttributeMaxDynamicSharedMemorySize, SM_128);
  cudaFuncSetAttribute(hgemm_kernel<64,1>,
      cudaFuncAttributeMaxDynamicSharedMemorySize, SM_64);

  // --- launch 1: qkvd + krb (both depend only on hs16) -> 576 blocks ---
  {
    GJobs J{};
    J.j[0] = {hs16, wqkv, nullptr, dA1, 1536,  384, 1536, 1,  6};
    J.j[1] = {hs16, wrk,  nullptr, krb, 1536,  768, 1536, 1, 12};
    J.bstart[0] = 0; J.bstart[1] = 192; J.bstart[2] = 576;
    hgemm_kernel<64,2><<<576, 256, SM_64>>>(J);
  }
  // --- launch 2: kc->kb | vf->vb | qc->qb | qr (scatter epilogues) ---
  {
    GJobs J{};
    J.j[0] = {dA1,     wkv,                  nullptr, kb, 384,  768, 192, 2,  6};
    J.j[1] = {dA1,     wkv + (size_t)768*192,nullptr, vb, 384, 1536, 192, 3, 12};
    J.j[2] = {dA1+192, wq,                   nullptr, qb, 384,  768, 192, 4,  6};
    J.j[3] = {dA1+192, wq  + (size_t)768*192,nullptr, qr, 384,  768, 192, 5,  6};
    J.bstart[0] = 0; J.bstart[1] = 192; J.bstart[2] = 576;
    J.bstart[3] = 768; J.bstart[4] = 960;
    hgemm_kernel<128,4><<<960, 256, SM_128>>>(J);
  }

  // rope-only assemble (upper 64 dims of q,k)
  assemble_kernel<<<dim3(Sn, Bn), 256>>>(qr, krb, rot, qb, kb);

  // flash attention: LPT dispatch
  cudaFuncSetAttribute(flash_kernel, cudaFuncAttributeMaxDynamicSharedMemorySize,
                       FLASH_SMEM);
  flash_kernel<<<dim3(Hn*Bn, 16), 256, FLASH_SMEM>>>(qb, kb, vb, at1);

  // --- output projection: BN=64 (768 blocks) ---
  {
    GJobs J{};
    J.j[0] = {at1, wob, out, nullptr, 1536, 1536, 1536, 0, 24};
    J.bstart[0] = 0; J.bstart[1] = 768;
    hgemm_kernel<64,1><<<768, 256, SM_64>>>(J);
  }
}